// round 3
// baseline (speedup 1.0000x reference)
#include <cuda_runtime.h>
#include <cstdint>

#define N_NODES 100000
#define N_EDGES 1250000
#define DFEAT   64
#define UNITS   64

#define SCAN_B  1024
#define NB_SCAN ((N_NODES + SCAN_B - 1) / SCAN_B)   // 98

// ---- scratch (device globals; allocation-free) ----
__device__ float4 g_U[(size_t)N_NODES * (UNITS / 4)];  // dinv[n] * (F[n] @ W), 25.6 MB
__device__ int    g_degi[N_NODES];
__device__ float  g_dinv[N_NODES];
__device__ int    g_scan[N_NODES];
__device__ int    g_bsum[NB_SCAN];
__device__ int    g_boff[NB_SCAN];
__device__ int    g_rowptr[N_NODES + 1];
__device__ int    g_fill[N_NODES];
__device__ int    g_col[N_EDGES];
__device__ int    g_is64;                              // edge_index dtype flag

// ---------------------------------------------------------------------------
// edge_index dtype detection: if buffer is int32, values read as int64 combine
// two random indices (lo + hi*2^32) and are far outside [0, N_NODES).
// ---------------------------------------------------------------------------
__global__ void k_detect(const void* __restrict__ ei) {
    if (threadIdx.x != 0 || blockIdx.x != 0) return;
    const long long* p = (const long long*)ei;
    int is64 = 1;
    for (int i = 0; i < 256; i++) {
        long long v = p[i];
        if (v < 0 || v >= N_NODES) { is64 = 0; break; }
    }
    g_is64 = is64;
}

__device__ __forceinline__ int edge_at(const void* __restrict__ ei, size_t idx) {
    if (g_is64) return (int)((const long long*)ei)[idx];
    return ((const int*)ei)[idx];
}

// ---------------------------------------------------------------------------
// 1) zero degree counters (graph replays must be self-contained)
// ---------------------------------------------------------------------------
__global__ void k_zero() {
    int i = blockIdx.x * blockDim.x + threadIdx.x;
    int stride = gridDim.x * blockDim.x;
    for (int j = i; j < N_NODES; j += stride) g_degi[j] = 0;
}

// ---------------------------------------------------------------------------
// 2) degree count
// ---------------------------------------------------------------------------
__global__ void k_degree(const void* __restrict__ ei) {
    int e = blockIdx.x * blockDim.x + threadIdx.x;
    if (e >= N_EDGES) return;
    int row = edge_at(ei, e);
    atomicAdd(&g_degi[row], 1);
}

// ---------------------------------------------------------------------------
// 3) dinv = deg > 0 ? rsqrt(deg) : 0
// ---------------------------------------------------------------------------
__global__ void k_dinv() {
    int i = blockIdx.x * blockDim.x + threadIdx.x;
    if (i >= N_NODES) return;
    int d = g_degi[i];
    g_dinv[i] = (d > 0) ? rsqrtf((float)d) : 0.f;
}

// ---------------------------------------------------------------------------
// 4) prefix scan of degrees (3 stages) -> exclusive rowptr
// ---------------------------------------------------------------------------
__global__ void k_scan_block() {
    __shared__ int s[SCAN_B];
    int tid = threadIdx.x;
    int i = blockIdx.x * SCAN_B + tid;
    int v = (i < N_NODES) ? g_degi[i] : 0;
    s[tid] = v;
    __syncthreads();
#pragma unroll
    for (int off = 1; off < SCAN_B; off <<= 1) {
        int t = (tid >= off) ? s[tid - off] : 0;
        __syncthreads();
        s[tid] += t;
        __syncthreads();
    }
    if (i < N_NODES) g_scan[i] = s[tid];
    if (tid == SCAN_B - 1) g_bsum[blockIdx.x] = s[tid];
}

__global__ void k_scan_bsums() {   // single block of 128 threads, NB_SCAN <= 128
    __shared__ int s[128];
    int tid = threadIdx.x;
    int v = (tid < NB_SCAN) ? g_bsum[tid] : 0;
    s[tid] = v;
    __syncthreads();
#pragma unroll
    for (int off = 1; off < 128; off <<= 1) {
        int t = (tid >= off) ? s[tid - off] : 0;
        __syncthreads();
        s[tid] += t;
        __syncthreads();
    }
    if (tid < NB_SCAN) g_boff[tid] = s[tid] - v;   // exclusive
}

__global__ void k_scan_add() {
    int i = blockIdx.x * blockDim.x + threadIdx.x;
    if (i >= N_NODES) return;
    int excl = g_scan[i] - g_degi[i] + g_boff[i / SCAN_B];
    g_rowptr[i] = excl;
    g_fill[i] = excl;
    if (i == 0) g_rowptr[N_NODES] = N_EDGES;
}

// ---------------------------------------------------------------------------
// 5) transform: U[n] = dinv[n] * (F[n] @ W)   (one thread per node)
// ---------------------------------------------------------------------------
__global__ void k_transform(const float* __restrict__ F,
                            const float* __restrict__ W) {
    __shared__ float4 Ws[DFEAT * (UNITS / 4)];  // 16 KB
    for (int i = threadIdx.x; i < DFEAT * (UNITS / 4); i += blockDim.x)
        Ws[i] = reinterpret_cast<const float4*>(W)[i];
    __syncthreads();

    int node = blockIdx.x * blockDim.x + threadIdx.x;
    if (node >= N_NODES) return;

    float4 acc[16];
#pragma unroll
    for (int j = 0; j < 16; j++) acc[j] = make_float4(0.f, 0.f, 0.f, 0.f);

    const float4* Frow = reinterpret_cast<const float4*>(F + (size_t)node * DFEAT);
#pragma unroll 4
    for (int k4 = 0; k4 < 16; k4++) {
        float4 f = Frow[k4];
        float fv[4] = {f.x, f.y, f.z, f.w};
#pragma unroll
        for (int kk = 0; kk < 4; kk++) {
            float p = fv[kk];
            const float4* wrow = &Ws[(k4 * 4 + kk) * 16];
#pragma unroll
            for (int j = 0; j < 16; j++) {
                float4 w = wrow[j];
                acc[j].x += p * w.x;
                acc[j].y += p * w.y;
                acc[j].z += p * w.z;
                acc[j].w += p * w.w;
            }
        }
    }
    float dv = g_dinv[node];
    float4* Urow = &g_U[(size_t)node * 16];
#pragma unroll
    for (int j = 0; j < 16; j++) {
        acc[j].x *= dv; acc[j].y *= dv; acc[j].z *= dv; acc[j].w *= dv;
        Urow[j] = acc[j];
    }
}

// ---------------------------------------------------------------------------
// 6) CSR fill: place col of each edge into its row's bucket
// ---------------------------------------------------------------------------
__global__ void k_fill(const void* __restrict__ ei) {
    int e = blockIdx.x * blockDim.x + threadIdx.x;
    if (e >= N_EDGES) return;
    int row = edge_at(ei, e);
    int col = edge_at(ei, (size_t)N_EDGES + e);
    int pos = atomicAdd(&g_fill[row], 1);
    g_col[pos] = col;
}

// ---------------------------------------------------------------------------
// 7) gather + epilogue: out[i] = relu(dinv[i] * sum_{e in row i} U[col_e] + b)
//    16 threads per node, one float4 column chunk each. No atomics.
// ---------------------------------------------------------------------------
__global__ void k_gather(float4* __restrict__ out4,
                         const float* __restrict__ bias) {
    int gid = blockIdx.x * blockDim.x + threadIdx.x;
    int node = gid >> 4;
    int c = gid & 15;
    if (node >= N_NODES) return;

    int start = g_rowptr[node];
    int end = g_rowptr[node + 1];

    float4 acc = make_float4(0.f, 0.f, 0.f, 0.f);
    int j = start;
    for (; j + 1 < end; j += 2) {
        int c0 = g_col[j];
        int c1 = g_col[j + 1];
        float4 a = g_U[c0 * 16 + c];
        float4 b = g_U[c1 * 16 + c];
        acc.x += a.x + b.x;
        acc.y += a.y + b.y;
        acc.z += a.z + b.z;
        acc.w += a.w + b.w;
    }
    if (j < end) {
        float4 a = g_U[g_col[j] * 16 + c];
        acc.x += a.x; acc.y += a.y; acc.z += a.z; acc.w += a.w;
    }

    float dv = g_dinv[node];
    float4 b4 = reinterpret_cast<const float4*>(bias)[c];
    float4 v;
    v.x = fmaxf(fmaf(dv, acc.x, b4.x), 0.f);
    v.y = fmaxf(fmaf(dv, acc.y, b4.y), 0.f);
    v.z = fmaxf(fmaf(dv, acc.z, b4.z), 0.f);
    v.w = fmaxf(fmaf(dv, acc.w, b4.w), 0.f);
    out4[node * 16 + c] = v;
}

// ---------------------------------------------------------------------------
extern "C" void kernel_launch(void* const* d_in, const int* in_sizes, int n_in,
                              void* d_out, int out_size) {
    const float* features = (const float*)d_in[0];       // [N, 64]
    const void*  edge_idx = d_in[1];                     // [2, E] int32 or int64
    const float* weight   = (const float*)d_in[2];       // [64, 64]
    const float* bias     = (const float*)d_in[3];       // [64]
    float4*      out4     = (float4*)d_out;              // [N, 64] fp32

    const int B = 256;

    k_detect<<<1, 32>>>(edge_idx);
    k_zero<<<512, B>>>();
    k_degree<<<(N_EDGES + B - 1) / B, B>>>(edge_idx);
    k_dinv<<<(N_NODES + B - 1) / B, B>>>();
    k_scan_block<<<NB_SCAN, SCAN_B>>>();
    k_scan_bsums<<<1, 128>>>();
    k_scan_add<<<(N_NODES + B - 1) / B, B>>>();
    k_transform<<<(N_NODES + B - 1) / B, B>>>(features, weight);
    k_fill<<<(N_EDGES + B - 1) / B, B>>>(edge_idx);
    k_gather<<<(N_NODES * 16 + B - 1) / B, B>>>(out4, bias);
}

// round 4
// speedup vs baseline: 1.0196x; 1.0196x over previous
#include <cuda_runtime.h>
#include <cstdint>

#define N_NODES 100000
#define N_EDGES 1250000
#define DFEAT   64
#define UNITS   64

#define SCAN_B  1024
#define NB_SCAN ((N_NODES + SCAN_B - 1) / SCAN_B)   // 98

// ---- scratch (device globals; allocation-free) ----
__device__ float4 g_U[(size_t)N_NODES * (UNITS / 4)];  // dinv[n] * (F[n] @ W), 25.6 MB
__device__ int    g_degi[N_NODES];
__device__ float  g_dinv[N_NODES];
__device__ int    g_scan[N_NODES];
__device__ int    g_bsum[NB_SCAN];
__device__ int    g_boff[NB_SCAN];
__device__ int    g_rowptr[N_NODES + 1];
__device__ int    g_fill[N_NODES];
__device__ int    g_col[N_EDGES];
__device__ int    g_is64;

// f32x2 packed FMA helpers (Blackwell FFMA2)
#define FMA_F32X2(acc, a, b) \
    asm("fma.rn.f32x2 %0, %1, %2, %0;" : "+l"(acc) : "l"(a), "l"(b))
#define PACK_DUP_F32X2(out, s) \
    asm("mov.b64 %0, {%1, %1};" : "=l"(out) : "r"(s))

// ---------------------------------------------------------------------------
// 1) zero degree counters + dtype detect (warp 0 of block 0)
//    int32 data read as int64 pairs two random indices -> out of [0, N_NODES)
// ---------------------------------------------------------------------------
__global__ void k_zero_detect(const void* __restrict__ ei) {
    int i = blockIdx.x * blockDim.x + threadIdx.x;
    int stride = gridDim.x * blockDim.x;
    for (int j = i; j < N_NODES; j += stride) g_degi[j] = 0;

    if (blockIdx.x == 0 && threadIdx.x < 32) {
        const long long* p = (const long long*)ei;
        int bad = 0;
#pragma unroll
        for (int k = 0; k < 8; k++) {
            long long v = p[threadIdx.x * 8 + k];
            bad |= (v < 0 || v >= N_NODES);
        }
        unsigned any = __ballot_sync(0xFFFFFFFFu, bad);
        if (threadIdx.x == 0) g_is64 = (any == 0u) ? 1 : 0;
    }
}

// ---------------------------------------------------------------------------
// 2) degree count: 4 edges per thread, vector loads
// ---------------------------------------------------------------------------
__global__ void k_degree(const void* __restrict__ ei) {
    int t = blockIdx.x * blockDim.x + threadIdx.x;
    int base = t * 4;
    if (base >= N_EDGES) return;
    int r[4];
    if (g_is64) {
        const longlong2* p = (const longlong2*)ei;
        longlong2 a = p[t * 2];
        longlong2 b = p[t * 2 + 1];
        r[0] = (int)a.x; r[1] = (int)a.y; r[2] = (int)b.x; r[3] = (int)b.y;
    } else {
        int4 a = ((const int4*)ei)[t];
        r[0] = a.x; r[1] = a.y; r[2] = a.z; r[3] = a.w;
    }
#pragma unroll
    for (int k = 0; k < 4; k++) atomicAdd(&g_degi[r[k]], 1);
}

// ---------------------------------------------------------------------------
// 3) prefix scan of degrees (3 stages) -> exclusive rowptr (+ dinv fused)
// ---------------------------------------------------------------------------
__global__ void k_scan_block() {
    __shared__ int s[SCAN_B];
    int tid = threadIdx.x;
    int i = blockIdx.x * SCAN_B + tid;
    int v = (i < N_NODES) ? g_degi[i] : 0;
    s[tid] = v;
    __syncthreads();
#pragma unroll
    for (int off = 1; off < SCAN_B; off <<= 1) {
        int t = (tid >= off) ? s[tid - off] : 0;
        __syncthreads();
        s[tid] += t;
        __syncthreads();
    }
    if (i < N_NODES) g_scan[i] = s[tid];
    if (tid == SCAN_B - 1) g_bsum[blockIdx.x] = s[tid];
}

__global__ void k_scan_bsums() {   // one block of 128 threads; NB_SCAN <= 128
    __shared__ int s[128];
    int tid = threadIdx.x;
    int v = (tid < NB_SCAN) ? g_bsum[tid] : 0;
    s[tid] = v;
    __syncthreads();
#pragma unroll
    for (int off = 1; off < 128; off <<= 1) {
        int t = (tid >= off) ? s[tid - off] : 0;
        __syncthreads();
        s[tid] += t;
        __syncthreads();
    }
    if (tid < NB_SCAN) g_boff[tid] = s[tid] - v;   // exclusive
}

__global__ void k_scan_add() {     // also computes dinv (fused)
    int i = blockIdx.x * blockDim.x + threadIdx.x;
    if (i >= N_NODES) return;
    int d = g_degi[i];
    int excl = g_scan[i] - d + g_boff[i / SCAN_B];
    g_rowptr[i] = excl;
    g_fill[i] = excl;
    g_dinv[i] = (d > 0) ? rsqrtf((float)d) : 0.f;
    if (i == 0) g_rowptr[N_NODES] = N_EDGES;
}

// ---------------------------------------------------------------------------
// 4) transform: U[n] = dinv[n] * (F[n] @ W)  — packed f32x2 FMA pipe
// ---------------------------------------------------------------------------
__global__ void k_transform(const float* __restrict__ F,
                            const float* __restrict__ W) {
    __shared__ float4 Ws[DFEAT * (UNITS / 4)];  // 16 KB
    for (int i = threadIdx.x; i < DFEAT * (UNITS / 4); i += blockDim.x)
        Ws[i] = reinterpret_cast<const float4*>(W)[i];
    __syncthreads();

    int node = blockIdx.x * blockDim.x + threadIdx.x;
    if (node >= N_NODES) return;

    unsigned long long acc[32];   // 32 f32x2 pairs = 64 outputs
#pragma unroll
    for (int j = 0; j < 32; j++) acc[j] = 0ull;  // (0.f, 0.f)

    const float4* Frow = reinterpret_cast<const float4*>(F + (size_t)node * DFEAT);
#pragma unroll 4
    for (int k4 = 0; k4 < 16; k4++) {
        float4 f = Frow[k4];
        float fv[4] = {f.x, f.y, f.z, f.w};
#pragma unroll
        for (int kk = 0; kk < 4; kk++) {
            unsigned long long p2;
            PACK_DUP_F32X2(p2, __float_as_uint(fv[kk]));
            const unsigned long long* wrow =
                reinterpret_cast<const unsigned long long*>(&Ws[(k4 * 4 + kk) * 16]);
#pragma unroll
            for (int j = 0; j < 32; j++) {
                FMA_F32X2(acc[j], p2, wrow[j]);
            }
        }
    }
    float dv = g_dinv[node];
    float4* Urow = &g_U[(size_t)node * 16];
#pragma unroll
    for (int j = 0; j < 16; j++) {
        float2 lo = *reinterpret_cast<float2*>(&acc[2 * j]);
        float2 hi = *reinterpret_cast<float2*>(&acc[2 * j + 1]);
        Urow[j] = make_float4(lo.x * dv, lo.y * dv, hi.x * dv, hi.y * dv);
    }
}

// ---------------------------------------------------------------------------
// 5) CSR fill: 4 edges per thread, vector loads
// ---------------------------------------------------------------------------
__global__ void k_fill(const void* __restrict__ ei) {
    int t = blockIdx.x * blockDim.x + threadIdx.x;
    int base = t * 4;
    if (base >= N_EDGES) return;
    int r[4], c[4];
    if (g_is64) {
        const longlong2* p = (const longlong2*)ei;
        longlong2 a = p[t * 2];
        longlong2 b = p[t * 2 + 1];
        r[0] = (int)a.x; r[1] = (int)a.y; r[2] = (int)b.x; r[3] = (int)b.y;
        const longlong2* q = (const longlong2*)((const long long*)ei + N_EDGES);
        longlong2 d = q[t * 2];
        longlong2 e = q[t * 2 + 1];
        c[0] = (int)d.x; c[1] = (int)d.y; c[2] = (int)e.x; c[3] = (int)e.y;
    } else {
        int4 a = ((const int4*)ei)[t];
        r[0] = a.x; r[1] = a.y; r[2] = a.z; r[3] = a.w;
        int4 d = ((const int4*)((const int*)ei + N_EDGES))[t];
        c[0] = d.x; c[1] = d.y; c[2] = d.z; c[3] = d.w;
    }
#pragma unroll
    for (int k = 0; k < 4; k++) {
        int pos = atomicAdd(&g_fill[r[k]], 1);
        g_col[pos] = c[k];
    }
}

// ---------------------------------------------------------------------------
// 6) gather + epilogue: out[i] = relu(dinv[i] * sum_{e in row i} U[col_e] + b)
//    16 threads per node, one float4 column chunk each. No atomics.
// ---------------------------------------------------------------------------
__global__ void k_gather(float4* __restrict__ out4,
                         const float* __restrict__ bias) {
    int gid = blockIdx.x * blockDim.x + threadIdx.x;
    int node = gid >> 4;
    int c = gid & 15;
    if (node >= N_NODES) return;

    int start = g_rowptr[node];
    int end = g_rowptr[node + 1];

    float4 acc0 = make_float4(0.f, 0.f, 0.f, 0.f);
    float4 acc1 = make_float4(0.f, 0.f, 0.f, 0.f);
    int j = start;
    for (; j + 3 < end; j += 4) {
        int c0 = g_col[j];
        int c1 = g_col[j + 1];
        int c2 = g_col[j + 2];
        int c3 = g_col[j + 3];
        float4 a = g_U[c0 * 16 + c];
        float4 b = g_U[c1 * 16 + c];
        float4 d = g_U[c2 * 16 + c];
        float4 e = g_U[c3 * 16 + c];
        acc0.x += a.x + b.x;  acc0.y += a.y + b.y;
        acc0.z += a.z + b.z;  acc0.w += a.w + b.w;
        acc1.x += d.x + e.x;  acc1.y += d.y + e.y;
        acc1.z += d.z + e.z;  acc1.w += d.w + e.w;
    }
    for (; j < end; j++) {
        float4 a = g_U[g_col[j] * 16 + c];
        acc0.x += a.x; acc0.y += a.y; acc0.z += a.z; acc0.w += a.w;
    }
    acc0.x += acc1.x; acc0.y += acc1.y; acc0.z += acc1.z; acc0.w += acc1.w;

    float dv = g_dinv[node];
    float4 b4 = reinterpret_cast<const float4*>(bias)[c];
    float4 v;
    v.x = fmaxf(fmaf(dv, acc0.x, b4.x), 0.f);
    v.y = fmaxf(fmaf(dv, acc0.y, b4.y), 0.f);
    v.z = fmaxf(fmaf(dv, acc0.z, b4.z), 0.f);
    v.w = fmaxf(fmaf(dv, acc0.w, b4.w), 0.f);
    out4[node * 16 + c] = v;
}

// ---------------------------------------------------------------------------
extern "C" void kernel_launch(void* const* d_in, const int* in_sizes, int n_in,
                              void* d_out, int out_size) {
    const float* features = (const float*)d_in[0];       // [N, 64]
    const void*  edge_idx = d_in[1];                     // [2, E] int32 or int64
    const float* weight   = (const float*)d_in[2];       // [64, 64]
    const float* bias     = (const float*)d_in[3];       // [64]
    float4*      out4     = (float4*)d_out;              // [N, 64] fp32

    const int B = 256;
    const int E4 = N_EDGES / 4;                          // 312500 (divisible)

    k_zero_detect<<<512, B>>>(edge_idx);
    k_degree<<<(E4 + B - 1) / B, B>>>(edge_idx);
    k_scan_block<<<NB_SCAN, SCAN_B>>>();
    k_scan_bsums<<<1, 128>>>();
    k_scan_add<<<(N_NODES + B - 1) / B, B>>>();
    k_transform<<<(N_NODES + B - 1) / B, B>>>(features, weight);
    k_fill<<<(E4 + B - 1) / B, B>>>(edge_idx);
    k_gather<<<(N_NODES * 16 + B - 1) / B, B>>>(out4, bias);
}